// round 9
// baseline (speedup 1.0000x reference)
#include <cuda_runtime.h>
#include <cuda_fp16.h>

typedef unsigned int u32;
typedef unsigned long long u64;

#define NE   8
#define DD   512
#define DFF  2048
#define NTOK 4096

// ---------------- device scratch (no allocation allowed) ----------------
__device__ __half g_x  [(size_t)NTOK*DD];
__device__ __half g_w1 [(size_t)NE*DFF*DD];     // W1^T per expert [2048,512]
__device__ __half g_w2 [(size_t)NE*DD*DFF];     // W2^T per expert [512,2048]
__device__ __half g_wq [DD*DD];
__device__ __half g_wkv[2*DD*DD];               // [Wk;Wv] rows concat -> [1024,512]
__device__ __half g_wo [DD*DD];
__device__ float  g_bkv[2*DD];
__device__ __half g_hid[(size_t)NE*NTOK*DFF];
__device__ __half g_eo [(size_t)NE*NTOK*DD];
__device__ __half g_kv [(size_t)NE*NTOK*2*DD];  // fp16: [e][tok][0:512]=k, [512:1024]=v
__device__ float  g_q  [(size_t)NTOK*DD];
__device__ __half g_cx [(size_t)NTOK*DD];

// ---------------- helpers ----------------
__device__ __forceinline__ u32 smem_u32(const void* p) {
    return (u32)__cvta_generic_to_shared(p);
}
__device__ __forceinline__ void cpa16(u32 dst, const void* src) {
    asm volatile("cp.async.cg.shared.global [%0], [%1], 16;" :: "r"(dst), "l"(src));
}
#define CPA_COMMIT() asm volatile("cp.async.commit_group;" ::: "memory")
#define CPA_WAIT1()  asm volatile("cp.async.wait_group 1;" ::: "memory")

__device__ __forceinline__ void ldsm_x4(u32* r, u32 addr) {
    asm volatile("ldmatrix.sync.aligned.m8n8.x4.shared.b16 {%0,%1,%2,%3}, [%4];"
                 : "=r"(r[0]), "=r"(r[1]), "=r"(r[2]), "=r"(r[3]) : "r"(addr));
}
__device__ __forceinline__ void ldsm_x2(u32* r, u32 addr) {
    asm volatile("ldmatrix.sync.aligned.m8n8.x2.shared.b16 {%0,%1}, [%2];"
                 : "=r"(r[0]), "=r"(r[1]) : "r"(addr));
}
__device__ __forceinline__ void mma16816(float* c, const u32* a, const u32* b) {
    asm volatile(
        "mma.sync.aligned.m16n8k16.row.col.f32.f16.f16.f32 "
        "{%0,%1,%2,%3}, {%4,%5,%6,%7}, {%8,%9}, {%0,%1,%2,%3};"
        : "+f"(c[0]), "+f"(c[1]), "+f"(c[2]), "+f"(c[3])
        : "r"(a[0]), "r"(a[1]), "r"(a[2]), "r"(a[3]), "r"(b[0]), "r"(b[1]));
}

// smem geometry: tile 128x128, ktile 64 (128B/row + 16 pad = 144B rows), slabs A,B
#define KTILE   64
#define ROWB    144
#define OFF_A   0
#define OFF_B   (128*ROWB)            // 18432
#define STAGEB  (2*128*ROWB)          // 36864
#define NSTAGE  2
#define SMEM_BYTES (NSTAGE * STAGEB)  // 73728 -> 2 CTAs/SM

// ---------------- fp16 mma.sync GEMM ----------------
// D[m,n] = sum_k A[m,k]*B[n,k] + bias[n]; A,B fp16 K-major rows, fp32 accum.
// Block tile 128x128, 8 warps (2x4), warp tile 64x32, ktile 64, double-buffered.
// OUTMODE: 0 -> fp32 Cf ; 1 -> fp16 Ch.
template<int OUTMODE, bool RELU>
__global__ void __launch_bounds__(256, 2) mma_gemm(
    const __half* __restrict__ A, const __half* __restrict__ B,
    const float* __restrict__ biasg,
    float* __restrict__ Cf, __half* __restrict__ Ch,
    int N, int K,
    size_t sA, size_t sB, size_t sBias, size_t sC,
    const int* __restrict__ eidPtr, size_t eidStride)
{
    extern __shared__ __align__(128) char sm[];
    const int tid  = threadIdx.x;
    const int lane = tid & 31;
    const int wid  = tid >> 5;
    const int e    = blockIdx.z;
    const int m0   = blockIdx.y * 128;
    const int n0   = blockIdx.x * 128;

    size_t aoff = (size_t)e * sA;
    if (eidPtr) aoff += (size_t)(*eidPtr) * eidStride;
    const __half* pA = A + aoff;
    const __half* pB = B + (size_t)e * sB;
    const float* bias = biasg + (size_t)e * sBias;

    const u32 smb = smem_u32(sm);

    // ---- loader mapping: 128 rows x 128B/slab, 2 threads/row, 4x16B each ----
    const int lr = tid >> 1;
    const int lc = (tid & 1) * 4;     // chunk base 0 or 4
    const __half* gA = pA + (size_t)(m0 + lr) * K + lc * 8;
    const __half* gB = pB + (size_t)(n0 + lr) * K + lc * 8;
    const u32 so = (u32)(lr * ROWB + lc * 16);

    // ---- warp/compute mapping: warps 2x4, warp tile 64x32 ----
    const int wm = wid >> 2;
    const int wn = wid & 3;

    u32 offA[4], offB[4];   // per-ks offsets added in loop (ks*32 bytes)
    {
        const int rA = wm * 64 + (lane & 15);
        const int cA = lane >> 4;
        #pragma unroll
        for (int im = 0; im < 4; im++)
            offA[im] = (u32)((rA + im * 16) * ROWB + cA * 16);
        const int rB = wn * 32 + (lane & 7);
        const int cB = (lane >> 3) & 1;
        #pragma unroll
        for (int in = 0; in < 4; in++)
            offB[in] = (u32)((rB + in * 8) * ROWB + cB * 16);
    }

    float acc[4][4][4];
    #pragma unroll
    for (int im = 0; im < 4; im++)
        #pragma unroll
        for (int in = 0; in < 4; in++)
            #pragma unroll
            for (int q = 0; q < 4; q++) acc[im][in][q] = 0.f;

    const int nt = K / KTILE;

    // ---- prologue: fill both stages ----
    #pragma unroll
    for (int p = 0; p < 2; p++) {
        const int k0 = p * KTILE;
        const u32 b = smb + p * STAGEB;
        #pragma unroll
        for (int c = 0; c < 4; c++) {
            cpa16(b + OFF_A + so + c * 16, gA + k0 + c * 8);
            cpa16(b + OFF_B + so + c * 16, gB + k0 + c * 8);
        }
        CPA_COMMIT();
    }

    for (int i = 0; i < nt; i++) {
        CPA_WAIT1();
        __syncthreads();

        const u32 stage = smb + (u32)(i & 1) * STAGEB;
        #pragma unroll
        for (int ks = 0; ks < 4; ks++) {
            const u32 ko = (u32)(ks * 32);
            u32 a[4][4];
            #pragma unroll
            for (int im = 0; im < 4; im++)
                ldsm_x4(a[im], stage + OFF_A + offA[im] + ko);
            u32 b[4][2];
            #pragma unroll
            for (int in = 0; in < 4; in++)
                ldsm_x2(b[in], stage + OFF_B + offB[in] + ko);
            #pragma unroll
            for (int im = 0; im < 4; im++)
                #pragma unroll
                for (int in = 0; in < 4; in++)
                    mma16816(acc[im][in], a[im], b[in]);
        }
        __syncthreads();

        const int inext = i + 2;
        if (inext < nt) {
            const int k0 = inext * KTILE;
            const u32 b = smb + (u32)(i & 1) * STAGEB;
            #pragma unroll
            for (int c = 0; c < 4; c++) {
                cpa16(b + OFF_A + so + c * 16, gA + k0 + c * 8);
                cpa16(b + OFF_B + so + c * 16, gB + k0 + c * 8);
            }
        }
        CPA_COMMIT();
    }

    // ---- epilogue ----
    const int g = lane >> 2;
    const int cb_in = (lane & 3) * 2;
    #pragma unroll
    for (int in = 0; in < 4; in++) {
        const int col = n0 + wn * 32 + in * 8 + cb_in;
        const float bx = bias[col], by = bias[col + 1];
        #pragma unroll
        for (int im = 0; im < 4; im++) {
            const int r0 = m0 + wm * 64 + im * 16 + g;
            const int r1 = r0 + 8;
            float v00 = acc[im][in][0] + bx, v01 = acc[im][in][1] + by;
            float v10 = acc[im][in][2] + bx, v11 = acc[im][in][3] + by;
            if (RELU) {
                v00 = fmaxf(v00, 0.f); v01 = fmaxf(v01, 0.f);
                v10 = fmaxf(v10, 0.f); v11 = fmaxf(v11, 0.f);
            }
            if (OUTMODE == 0) {
                float* o = Cf + (size_t)e * sC;
                float2 a0 = {v00, v01}, a1 = {v10, v11};
                *(float2*)(o + (size_t)r0 * N + col) = a0;
                *(float2*)(o + (size_t)r1 * N + col) = a1;
            } else {
                __half* oh = Ch + (size_t)e * sC;
                __half2 p;
                p.x = __float2half_rn(v00); p.y = __float2half_rn(v01);
                *(__half2*)(oh + (size_t)r0 * N + col) = p;
                p.x = __float2half_rn(v10); p.y = __float2half_rn(v11);
                *(__half2*)(oh + (size_t)r1 * N + col) = p;
            }
        }
    }
}

// ---------------- conversion kernels ----------------
__global__ void k_half(const float* __restrict__ in, __half* __restrict__ out, int n4)
{
    const int i = blockIdx.x * 256 + threadIdx.x;
    if (i >= n4) return;
    const float4 u = ((const float4*)in)[i];
    __half h[4];
    h[0] = __float2half_rn(u.x); h[1] = __float2half_rn(u.y);
    h[2] = __float2half_rn(u.z); h[3] = __float2half_rn(u.w);
    ((uint2*)out)[i] = *(const uint2*)h;
}

__global__ void k_cat_bias(const float* __restrict__ a, const float* __restrict__ b,
                           float* __restrict__ o)
{
    const int i = threadIdx.x + blockIdx.x * 256;
    if (i < DD) o[i] = a[i];
    else if (i < 2 * DD) o[i] = b[i - DD];
}

// transpose + convert: in [R,C] fp32 (batched over z) -> out [C,R] fp16
__global__ void k_thalf(const float* __restrict__ in, __half* __restrict__ out,
                        int R, int C)
{
    __shared__ float t[32][33];
    const size_t zo = (size_t)blockIdx.z * R * C;
    const int c0 = blockIdx.x * 32, r0 = blockIdx.y * 32;
    const int tx = threadIdx.x, ty = threadIdx.y;
    #pragma unroll
    for (int rr = ty; rr < 32; rr += 8)
        t[rr][tx] = in[zo + (size_t)(r0 + rr) * C + c0 + tx];
    __syncthreads();
    #pragma unroll
    for (int cc = ty; cc < 32; cc += 8)
        out[zo + (size_t)(c0 + cc) * R + r0 + tx] = __float2half_rn(t[tx][cc]);
}

// ---------------- attention over the expert axis (E=8), fp16 kv ----------------
__global__ void attn_kernel(const float* __restrict__ q,
                            const __half* __restrict__ kvbuf,
                            __half* __restrict__ ctx,
                            const int* __restrict__ eidPtr)
{
    const int n    = blockIdx.x;
    const int head = threadIdx.x >> 5;
    const int lane = threadIdx.x & 31;
    const int eid  = *eidPtr;

    const int hb   = head * 64 + 2 * lane;
    const float2 qv = *(const float2*)(q + n * DD + hb);
    const __half* kvn = kvbuf + (size_t)n * 2 * DD;

    float s[NE];
    #pragma unroll
    for (int f = 0; f < NE; f++) {
        const __half2 kh = *(const __half2*)(kvn + (size_t)f * NTOK * 2 * DD + hb);
        const float2 kv = __half22float2(kh);
        float p = qv.x * kv.x + qv.y * kv.y;
        #pragma unroll
        for (int off = 16; off > 0; off >>= 1)
            p += __shfl_xor_sync(0xffffffffu, p, off);
        s[f] = p * 0.125f + ((f <= eid) ? 1.0f : 0.0f);
    }

    float mx = s[0];
    #pragma unroll
    for (int f = 1; f < NE; f++) mx = fmaxf(mx, s[f]);
    float sum = 0.f;
    #pragma unroll
    for (int f = 0; f < NE; f++) { s[f] = expf(s[f] - mx); sum += s[f]; }
    const float inv = 1.f / sum;

    float cx = 0.f, cy = 0.f;
    #pragma unroll
    for (int f = 0; f < NE; f++) {
        const __half2 vh = *(const __half2*)(kvn + (size_t)f * NTOK * 2 * DD + DD + hb);
        const float2 vv = __half22float2(vh);
        const float p = s[f] * inv;
        cx += p * vv.x; cy += p * vv.y;
    }
    __half2 o;
    o.x = __float2half_rn(cx); o.y = __float2half_rn(cy);
    *(__half2*)(ctx + n * DD + hb) = o;
}

// -----------------------------------------------------------------------------
extern "C" void kernel_launch(void* const* d_in, const int* in_sizes, int n_in,
                              void* d_out, int out_size)
{
    const float* x  = (const float*)d_in[0];
    const float* W1 = (const float*)d_in[1];
    const float* b1 = (const float*)d_in[2];
    const float* W2 = (const float*)d_in[3];
    const float* b2 = (const float*)d_in[4];
    const float* Wq = (const float*)d_in[5];
    const float* bq = (const float*)d_in[6];
    const float* Wk = (const float*)d_in[7];
    const float* bk = (const float*)d_in[8];
    const float* Wv = (const float*)d_in[9];
    const float* bv = (const float*)d_in[10];
    const float* Wo = (const float*)d_in[11];
    const float* bo = (const float*)d_in[12];
    const int*  eid = (const int*)  d_in[13];

    __half *xh, *w1, *w2, *wq, *wkv, *wo, *hid, *eo, *cx, *kvb;
    float *qb, *bkv;
    cudaGetSymbolAddress((void**)&xh,  g_x);
    cudaGetSymbolAddress((void**)&w1,  g_w1);
    cudaGetSymbolAddress((void**)&w2,  g_w2);
    cudaGetSymbolAddress((void**)&wq,  g_wq);
    cudaGetSymbolAddress((void**)&wkv, g_wkv);
    cudaGetSymbolAddress((void**)&wo,  g_wo);
    cudaGetSymbolAddress((void**)&hid, g_hid);
    cudaGetSymbolAddress((void**)&eo,  g_eo);
    cudaGetSymbolAddress((void**)&cx,  g_cx);
    cudaGetSymbolAddress((void**)&kvb, g_kv);
    cudaGetSymbolAddress((void**)&qb,  g_q);
    cudaGetSymbolAddress((void**)&bkv, g_bkv);

    cudaFuncSetAttribute(mma_gemm<0, false>, cudaFuncAttributeMaxDynamicSharedMemorySize, SMEM_BYTES);
    cudaFuncSetAttribute(mma_gemm<1, false>, cudaFuncAttributeMaxDynamicSharedMemorySize, SMEM_BYTES);
    cudaFuncSetAttribute(mma_gemm<1, true>,  cudaFuncAttributeMaxDynamicSharedMemorySize, SMEM_BYTES);

    // ---- launches 1-4: conversions; 5/6 are FFN1/FFN2 (ncu -s 5 -c 1 target) ----
    k_half<<<(NTOK * DD / 4 + 255) / 256, 256>>>(x, xh, NTOK * DD / 4);             // 1
    {   // 2: W1 [E,512,2048] -> [E,2048,512]
        dim3 g(DFF / 32, DD / 32, NE), b(32, 8);
        k_thalf<<<g, b>>>(W1, w1, DD, DFF);
    }
    {   // 3: W2 [E,2048,512] -> [E,512,2048]
        dim3 g(DD / 32, DFF / 32, NE), b(32, 8);
        k_thalf<<<g, b>>>(W2, w2, DFF, DD);
    }
    k_half<<<(DD * DD / 4 + 255) / 256, 256>>>(Wk, wkv, DD * DD / 4);               // 4

    // ---- 5: FFN1: hidden[e] = relu(x @ W1[e] + b1[e])  M=4096, N=2048, K=512 ----
    mma_gemm<1, true><<<dim3(DFF / 128, NTOK / 128, NE), 256, SMEM_BYTES>>>(
        xh, w1, b1, nullptr, hid,
        DFF, DD, 0, (size_t)DFF * DD, DFF, (size_t)NTOK * DFF, nullptr, 0);

    // ---- 6: FFN2: eo[e] = hidden[e] @ W2[e] + b2[e]  N=512, K=2048 ----
    mma_gemm<1, false><<<dim3(DD / 128, NTOK / 128, NE), 256, SMEM_BYTES>>>(
        hid, w2, b2, nullptr, eo,
        DD, DFF, (size_t)NTOK * DFF, (size_t)DD * DFF, DD, (size_t)NTOK * DD, nullptr, 0);

    // ---- remaining conversions ----
    k_half<<<(DD * DD / 4 + 255) / 256, 256>>>(Wv, wkv + DD * DD, DD * DD / 4);
    k_half<<<(DD * DD / 4 + 255) / 256, 256>>>(Wq, wq, DD * DD / 4);
    k_half<<<(DD * DD / 4 + 255) / 256, 256>>>(Wo, wo, DD * DD / 4);
    k_cat_bias<<<4, 256>>>(bk, bv, bkv);

    // ---- KV proj (fused, fp16 out): kv[e] = eo[e] @ [Wk;Wv]^T + [bk;bv] ----
    mma_gemm<1, false><<<dim3(2 * DD / 128, NTOK / 128, NE), 256, SMEM_BYTES>>>(
        eo, wkv, bkv, nullptr, kvb,
        2 * DD, DD, (size_t)NTOK * DD, 0, 0, (size_t)NTOK * 2 * DD, nullptr, 0);

    // ---- Q proj (expert_id slice only, fp32 out) ----
    mma_gemm<0, false><<<dim3(DD / 128, NTOK / 128, 1), 256, SMEM_BYTES>>>(
        eo, wq, bq, qb, nullptr,
        DD, DD, 0, 0, 0, 0, eid, (size_t)NTOK * DD);

    // ---- attention over experts ----
    attn_kernel<<<NTOK, 256>>>(qb, kvb, cx, eid);

    // ---- out proj: d_out = ctx @ Wo^T + bo ----
    mma_gemm<0, false><<<dim3(DD / 128, NTOK / 128, 1), 256, SMEM_BYTES>>>(
        cx, wo, bo, (float*)d_out, nullptr,
        DD, DD, 0, 0, 0, 0, nullptr, 0);
}

// round 10
// speedup vs baseline: 1.1746x; 1.1746x over previous
#include <cuda_runtime.h>
#include <cuda_fp16.h>

typedef unsigned int u32;
typedef unsigned long long u64;

#define NE   8
#define DD   512
#define DFF  2048
#define NTOK 4096

// ---------------- device scratch (no allocation allowed) ----------------
__device__ __half g_x  [(size_t)NTOK*DD];
__device__ __half g_w1 [(size_t)NE*DFF*DD];     // W1^T per expert [2048,512]
__device__ __half g_w2 [(size_t)NE*DD*DFF];     // W2^T per expert [512,2048]
__device__ __half g_wq [DD*DD];
__device__ __half g_wkv[2*DD*DD];               // [Wk;Wv] rows concat -> [1024,512]
__device__ __half g_wo [DD*DD];
__device__ float  g_bkv[2*DD];
__device__ __half g_hid[(size_t)NE*NTOK*DFF];
__device__ __half g_eo [(size_t)NE*NTOK*DD];
__device__ __half g_kv [(size_t)NE*NTOK*2*DD];  // fp16: [e][tok][0:512]=k, [512:1024]=v
__device__ float  g_q  [(size_t)NTOK*DD];
__device__ __half g_cx [(size_t)NTOK*DD];

// ---------------- helpers ----------------
__device__ __forceinline__ u32 smem_u32(const void* p) {
    return (u32)__cvta_generic_to_shared(p);
}
__device__ __forceinline__ void cpa16(u32 dst, const void* src) {
    asm volatile("cp.async.cg.shared.global [%0], [%1], 16;" :: "r"(dst), "l"(src));
}
#define CPA_COMMIT() asm volatile("cp.async.commit_group;" ::: "memory")
#define CPA_WAIT1()  asm volatile("cp.async.wait_group 1;" ::: "memory")

__device__ __forceinline__ void ldsm_x4(u32* r, u32 addr) {
    asm volatile("ldmatrix.sync.aligned.m8n8.x4.shared.b16 {%0,%1,%2,%3}, [%4];"
                 : "=r"(r[0]), "=r"(r[1]), "=r"(r[2]), "=r"(r[3]) : "r"(addr));
}
__device__ __forceinline__ void ldsm_x2(u32* r, u32 addr) {
    asm volatile("ldmatrix.sync.aligned.m8n8.x2.shared.b16 {%0,%1}, [%2];"
                 : "=r"(r[0]), "=r"(r[1]) : "r"(addr));
}
__device__ __forceinline__ void mma16816(float* c, const u32* a, const u32* b) {
    asm volatile(
        "mma.sync.aligned.m16n8k16.row.col.f32.f16.f16.f32 "
        "{%0,%1,%2,%3}, {%4,%5,%6,%7}, {%8,%9}, {%0,%1,%2,%3};"
        : "+f"(c[0]), "+f"(c[1]), "+f"(c[2]), "+f"(c[3])
        : "r"(a[0]), "r"(a[1]), "r"(a[2]), "r"(a[3]), "r"(b[0]), "r"(b[1]));
}

// smem geometry: tile 128x128, ktile 32 (64B/row + 16 pad = 80B rows), slabs A,B
#define KTILE   32
#define ROWB    80
#define OFF_A   0
#define OFF_B   (128*ROWB)           // 10240
#define STAGEB  (2*128*ROWB)         // 20480
#define NSTAGE  2
#define SMEM_BYTES (NSTAGE * STAGEB) // 40960 -> 2 CTAs/SM

// ---------------- fp16 mma.sync GEMM (round-7 proven config) ----------------
// D[m,n] = sum_k A[m,k]*B[n,k] + bias[n]; A,B fp16 K-major rows, fp32 accum.
// Block tile 128x128, 8 warps (2x4), warp tile 64x32, double-buffered cp.async.
// OUTMODE: 0 -> fp32 Cf ; 1 -> fp16 Ch.
template<int OUTMODE, bool RELU>
__global__ void __launch_bounds__(256, 2) mma_gemm(
    const __half* __restrict__ A, const __half* __restrict__ B,
    const float* __restrict__ biasg,
    float* __restrict__ Cf, __half* __restrict__ Ch,
    int N, int K,
    size_t sA, size_t sB, size_t sBias, size_t sC,
    const int* __restrict__ eidPtr, size_t eidStride)
{
    extern __shared__ __align__(128) char sm[];
    const int tid  = threadIdx.x;
    const int lane = tid & 31;
    const int wid  = tid >> 5;
    const int e    = blockIdx.z;
    const int m0   = blockIdx.y * 128;
    const int n0   = blockIdx.x * 128;

    size_t aoff = (size_t)e * sA;
    if (eidPtr) aoff += (size_t)(*eidPtr) * eidStride;
    const __half* pA = A + aoff;
    const __half* pB = B + (size_t)e * sB;
    const float* bias = biasg + (size_t)e * sBias;

    const u32 smb = smem_u32(sm);

    // ---- loader mapping: 128 rows x 64B/slab, 2 threads/row, 2x16B per slab ----
    const int lr = tid >> 1;
    const int lc = (tid & 1) * 2;
    const __half* gA = pA + (size_t)(m0 + lr) * K + lc * 8;
    const __half* gB = pB + (size_t)(n0 + lr) * K + lc * 8;
    const u32 so = (u32)(lr * ROWB + lc * 16);

    // ---- warp/compute mapping: warps 2x4, warp tile 64x32 ----
    const int wm = wid >> 2;
    const int wn = wid & 3;

    u32 offA[4][2], offB[4][2];
    {
        const int rA = wm * 64 + (lane & 15);
        const int cA = lane >> 4;
        #pragma unroll
        for (int im = 0; im < 4; im++)
            #pragma unroll
            for (int ks = 0; ks < 2; ks++)
                offA[im][ks] = (u32)((rA + im * 16) * ROWB + (ks * 2 + cA) * 16);
        const int rB = wn * 32 + (lane & 7);
        const int cB = (lane >> 3) & 1;
        #pragma unroll
        for (int in = 0; in < 4; in++)
            #pragma unroll
            for (int ks = 0; ks < 2; ks++)
                offB[in][ks] = (u32)((rB + in * 8) * ROWB + (ks * 2 + cB) * 16);
    }

    float acc[4][4][4];
    #pragma unroll
    for (int im = 0; im < 4; im++)
        #pragma unroll
        for (int in = 0; in < 4; in++)
            #pragma unroll
            for (int q = 0; q < 4; q++) acc[im][in][q] = 0.f;

    const int nt = K >> 5;

    // ---- prologue: fill both stages ----
    #pragma unroll
    for (int p = 0; p < 2; p++) {
        const int k0 = p * KTILE;
        const u32 b = smb + p * STAGEB;
        cpa16(b + OFF_A + so,      gA + k0);
        cpa16(b + OFF_A + so + 16, gA + k0 + 8);
        cpa16(b + OFF_B + so,      gB + k0);
        cpa16(b + OFF_B + so + 16, gB + k0 + 8);
        CPA_COMMIT();
    }

    for (int i = 0; i < nt; i++) {
        CPA_WAIT1();
        __syncthreads();

        const u32 stage = smb + (u32)(i & 1) * STAGEB;
        #pragma unroll
        for (int ks = 0; ks < 2; ks++) {
            u32 a[4][4];
            #pragma unroll
            for (int im = 0; im < 4; im++)
                ldsm_x4(a[im], stage + OFF_A + offA[im][ks]);
            u32 b[4][2];
            #pragma unroll
            for (int in = 0; in < 4; in++)
                ldsm_x2(b[in], stage + OFF_B + offB[in][ks]);
            #pragma unroll
            for (int im = 0; im < 4; im++)
                #pragma unroll
                for (int in = 0; in < 4; in++)
                    mma16816(acc[im][in], a[im], b[in]);
        }
        __syncthreads();

        const int inext = i + 2;
        if (inext < nt) {
            const int k0 = inext * KTILE;
            const u32 b = smb + (u32)(i & 1) * STAGEB;
            cpa16(b + OFF_A + so,      gA + k0);
            cpa16(b + OFF_A + so + 16, gA + k0 + 8);
            cpa16(b + OFF_B + so,      gB + k0);
            cpa16(b + OFF_B + so + 16, gB + k0 + 8);
        }
        CPA_COMMIT();
    }

    // ---- epilogue ----
    const int g = lane >> 2;
    const int cb_in = (lane & 3) * 2;
    #pragma unroll
    for (int in = 0; in < 4; in++) {
        const int col = n0 + wn * 32 + in * 8 + cb_in;
        const float bx = bias[col], by = bias[col + 1];
        #pragma unroll
        for (int im = 0; im < 4; im++) {
            const int r0 = m0 + wm * 64 + im * 16 + g;
            const int r1 = r0 + 8;
            float v00 = acc[im][in][0] + bx, v01 = acc[im][in][1] + by;
            float v10 = acc[im][in][2] + bx, v11 = acc[im][in][3] + by;
            if (RELU) {
                v00 = fmaxf(v00, 0.f); v01 = fmaxf(v01, 0.f);
                v10 = fmaxf(v10, 0.f); v11 = fmaxf(v11, 0.f);
            }
            if (OUTMODE == 0) {
                float* o = Cf + (size_t)e * sC;
                float2 a0 = {v00, v01}, a1 = {v10, v11};
                *(float2*)(o + (size_t)r0 * N + col) = a0;
                *(float2*)(o + (size_t)r1 * N + col) = a1;
            } else {
                __half* oh = Ch + (size_t)e * sC;
                __half2 p;
                p.x = __float2half_rn(v00); p.y = __float2half_rn(v01);
                *(__half2*)(oh + (size_t)r0 * N + col) = p;
                p.x = __float2half_rn(v10); p.y = __float2half_rn(v11);
                *(__half2*)(oh + (size_t)r1 * N + col) = p;
            }
        }
    }
}

// ---------------- conversion kernels ----------------
__global__ void k_half(const float* __restrict__ in, __half* __restrict__ out, int n4)
{
    const int i = blockIdx.x * 256 + threadIdx.x;
    if (i >= n4) return;
    const float4 u = ((const float4*)in)[i];
    __half h[4];
    h[0] = __float2half_rn(u.x); h[1] = __float2half_rn(u.y);
    h[2] = __float2half_rn(u.z); h[3] = __float2half_rn(u.w);
    ((uint2*)out)[i] = *(const uint2*)h;
}

__global__ void k_cat_bias(const float* __restrict__ a, const float* __restrict__ b,
                           float* __restrict__ o)
{
    const int i = threadIdx.x + blockIdx.x * 256;
    if (i < DD) o[i] = a[i];
    else if (i < 2 * DD) o[i] = b[i - DD];
}

// transpose + convert: in [R,C] fp32 (batched over z) -> out [C,R] fp16
__global__ void k_thalf(const float* __restrict__ in, __half* __restrict__ out,
                        int R, int C)
{
    __shared__ float t[32][33];
    const size_t zo = (size_t)blockIdx.z * R * C;
    const int c0 = blockIdx.x * 32, r0 = blockIdx.y * 32;
    const int tx = threadIdx.x, ty = threadIdx.y;
    #pragma unroll
    for (int rr = ty; rr < 32; rr += 8)
        t[rr][tx] = in[zo + (size_t)(r0 + rr) * C + c0 + tx];
    __syncthreads();
    #pragma unroll
    for (int cc = ty; cc < 32; cc += 8)
        out[zo + (size_t)(c0 + cc) * R + r0 + tx] = __float2half_rn(t[tx][cc]);
}

// ---------------- attention over the expert axis (E=8), fp16 kv ----------------
__global__ void attn_kernel(const float* __restrict__ q,
                            const __half* __restrict__ kvbuf,
                            __half* __restrict__ ctx,
                            const int* __restrict__ eidPtr)
{
    const int n    = blockIdx.x;
    const int head = threadIdx.x >> 5;
    const int lane = threadIdx.x & 31;
    const int eid  = *eidPtr;

    const int hb   = head * 64 + 2 * lane;
    const float2 qv = *(const float2*)(q + n * DD + hb);
    const __half* kvn = kvbuf + (size_t)n * 2 * DD;

    float s[NE];
    #pragma unroll
    for (int f = 0; f < NE; f++) {
        const __half2 kh = *(const __half2*)(kvn + (size_t)f * NTOK * 2 * DD + hb);
        const float2 kv = __half22float2(kh);
        float p = qv.x * kv.x + qv.y * kv.y;
        #pragma unroll
        for (int off = 16; off > 0; off >>= 1)
            p += __shfl_xor_sync(0xffffffffu, p, off);
        s[f] = p * 0.125f + ((f <= eid) ? 1.0f : 0.0f);
    }

    float mx = s[0];
    #pragma unroll
    for (int f = 1; f < NE; f++) mx = fmaxf(mx, s[f]);
    float sum = 0.f;
    #pragma unroll
    for (int f = 0; f < NE; f++) { s[f] = expf(s[f] - mx); sum += s[f]; }
    const float inv = 1.f / sum;

    float cx = 0.f, cy = 0.f;
    #pragma unroll
    for (int f = 0; f < NE; f++) {
        const __half2 vh = *(const __half2*)(kvn + (size_t)f * NTOK * 2 * DD + DD + hb);
        const float2 vv = __half22float2(vh);
        const float p = s[f] * inv;
        cx += p * vv.x; cy += p * vv.y;
    }
    __half2 o;
    o.x = __float2half_rn(cx); o.y = __float2half_rn(cy);
    *(__half2*)(ctx + n * DD + hb) = o;
}

// -----------------------------------------------------------------------------
extern "C" void kernel_launch(void* const* d_in, const int* in_sizes, int n_in,
                              void* d_out, int out_size)
{
    const float* x  = (const float*)d_in[0];
    const float* W1 = (const float*)d_in[1];
    const float* b1 = (const float*)d_in[2];
    const float* W2 = (const float*)d_in[3];
    const float* b2 = (const float*)d_in[4];
    const float* Wq = (const float*)d_in[5];
    const float* bq = (const float*)d_in[6];
    const float* Wk = (const float*)d_in[7];
    const float* bk = (const float*)d_in[8];
    const float* Wv = (const float*)d_in[9];
    const float* bv = (const float*)d_in[10];
    const float* Wo = (const float*)d_in[11];
    const float* bo = (const float*)d_in[12];
    const int*  eid = (const int*)  d_in[13];

    __half *xh, *w1, *w2, *wq, *wkv, *wo, *hid, *eo, *cx, *kvb;
    float *qb, *bkv;
    cudaGetSymbolAddress((void**)&xh,  g_x);
    cudaGetSymbolAddress((void**)&w1,  g_w1);
    cudaGetSymbolAddress((void**)&w2,  g_w2);
    cudaGetSymbolAddress((void**)&wq,  g_wq);
    cudaGetSymbolAddress((void**)&wkv, g_wkv);
    cudaGetSymbolAddress((void**)&wo,  g_wo);
    cudaGetSymbolAddress((void**)&hid, g_hid);
    cudaGetSymbolAddress((void**)&eo,  g_eo);
    cudaGetSymbolAddress((void**)&cx,  g_cx);
    cudaGetSymbolAddress((void**)&kvb, g_kv);
    cudaGetSymbolAddress((void**)&qb,  g_q);
    cudaGetSymbolAddress((void**)&bkv, g_bkv);

    cudaFuncSetAttribute(mma_gemm<0, false>, cudaFuncAttributeMaxDynamicSharedMemorySize, SMEM_BYTES);
    cudaFuncSetAttribute(mma_gemm<1, false>, cudaFuncAttributeMaxDynamicSharedMemorySize, SMEM_BYTES);
    cudaFuncSetAttribute(mma_gemm<1, true>,  cudaFuncAttributeMaxDynamicSharedMemorySize, SMEM_BYTES);

    // ---- launches 1-4: conversions; 5/6 are FFN1/FFN2 (ncu -s 5 -c 1 target) ----
    k_half<<<(NTOK * DD / 4 + 255) / 256, 256>>>(x, xh, NTOK * DD / 4);             // 1
    {   // 2: W1 [E,512,2048] -> [E,2048,512]
        dim3 g(DFF / 32, DD / 32, NE), b(32, 8);
        k_thalf<<<g, b>>>(W1, w1, DD, DFF);
    }
    {   // 3: W2 [E,2048,512] -> [E,512,2048]
        dim3 g(DD / 32, DFF / 32, NE), b(32, 8);
        k_thalf<<<g, b>>>(W2, w2, DFF, DD);
    }
    k_half<<<(DD * DD / 4 + 255) / 256, 256>>>(Wk, wkv, DD * DD / 4);               // 4

    // ---- 5: FFN1: hidden[e] = relu(x @ W1[e] + b1[e])  M=4096, N=2048, K=512 ----
    mma_gemm<1, true><<<dim3(DFF / 128, NTOK / 128, NE), 256, SMEM_BYTES>>>(
        xh, w1, b1, nullptr, hid,
        DFF, DD, 0, (size_t)DFF * DD, DFF, (size_t)NTOK * DFF, nullptr, 0);

    // ---- 6: FFN2: eo[e] = hidden[e] @ W2[e] + b2[e]  N=512, K=2048 ----
    mma_gemm<1, false><<<dim3(DD / 128, NTOK / 128, NE), 256, SMEM_BYTES>>>(
        hid, w2, b2, nullptr, eo,
        DD, DFF, (size_t)NTOK * DFF, (size_t)DD * DFF, DD, (size_t)NTOK * DD, nullptr, 0);

    // ---- remaining conversions ----
    k_half<<<(DD * DD / 4 + 255) / 256, 256>>>(Wv, wkv + DD * DD, DD * DD / 4);
    k_half<<<(DD * DD / 4 + 255) / 256, 256>>>(Wq, wq, DD * DD / 4);
    k_half<<<(DD * DD / 4 + 255) / 256, 256>>>(Wo, wo, DD * DD / 4);
    k_cat_bias<<<4, 256>>>(bk, bv, bkv);

    // ---- KV proj (fused, fp16 out): kv[e] = eo[e] @ [Wk;Wv]^T + [bk;bv] ----
    mma_gemm<1, false><<<dim3(2 * DD / 128, NTOK / 128, NE), 256, SMEM_BYTES>>>(
        eo, wkv, bkv, nullptr, kvb,
        2 * DD, DD, (size_t)NTOK * DD, 0, 0, (size_t)NTOK * 2 * DD, nullptr, 0);

    // ---- Q proj (expert_id slice only, fp32 out) ----
    mma_gemm<0, false><<<dim3(DD / 128, NTOK / 128, 1), 256, SMEM_BYTES>>>(
        eo, wq, bq, qb, nullptr,
        DD, DD, 0, 0, 0, 0, eid, (size_t)NTOK * DD);

    // ---- attention over experts ----
    attn_kernel<<<NTOK, 256>>>(qb, kvb, cx, eid);

    // ---- out proj: d_out = ctx @ Wo^T + bo ----
    mma_gemm<0, false><<<dim3(DD / 128, NTOK / 128, 1), 256, SMEM_BYTES>>>(
        cx, wo, bo, (float*)d_out, nullptr,
        DD, DD, 0, 0, 0, 0, nullptr, 0);
}